// round 8
// baseline (speedup 1.0000x reference)
#include <cuda_runtime.h>
#include <cuda_fp16.h>

#define NN   100000
#define EE   1600000
#define TW   12
#define CI_N 16
#define CMID 32
#define COUT 32

#define NSCAN 98                      // ceil(NN/1024)

// ---- scratch (allocation-free rule: __device__ globals) ----
__device__ float  g_deg[NN];
__device__ int    g_cnt[NN];
__device__ int    g_off[NN + 1];
__device__ int    g_cur[NN];
__device__ unsigned long long g_stat[NSCAN];         // decoupled-lookback state
__device__ float2 g_edge[EE];                        // (src as int bits, norm)
__device__ __half g_xsh[(size_t)NN * TW * CI_N];     // x node-major fp16
__device__ float  g_ax [(size_t)NN * TW * CI_N];     // aggregated x fp32
__device__ float  g_M  [TW * 3 * CI_N * COUT];       // fused gcn_w @ conv_w
__device__ float  g_B  [TW * COUT];                  // fused bias

// ---- packed f32x2 helpers (Blackwell FFMA2) ----
__device__ __forceinline__ void upk2(float& lo, float& hi, unsigned long long v) {
    asm("mov.b64 {%0, %1}, %2;" : "=f"(lo), "=f"(hi) : "l"(v));
}
__device__ __forceinline__ unsigned long long fma2(unsigned long long a,
                                                   unsigned long long b,
                                                   unsigned long long c) {
    unsigned long long d;
    asm("fma.rn.f32x2 %0, %1, %2, %3;" : "=l"(d) : "l"(a), "l"(b), "l"(c));
    return d;
}

// ================= K1: mega (deg histogram | x transpose | weight fuse | bias) ========
#define NB_E 6250                      // 6250*256 == EE
#define NB_X 4688                      // covers TW*NN = 1.2M
#define NB_F 72
#define NB_B 2
__global__ void k_mega(const float* __restrict__ x, const int* __restrict__ A,
                       const float* __restrict__ ew, const float* __restrict__ gw,
                       const float* __restrict__ cw, const float* __restrict__ gb,
                       const float* __restrict__ cb) {
    const int b = blockIdx.x, tid = threadIdx.x;
    if (b < NB_E) {
        int e = b * 256 + tid;
        int c = A[EE + e];
        atomicAdd(&g_deg[c], ew[e]);
        atomicAdd(&g_cnt[c], 1);
    } else if (b < NB_E + NB_X) {
        int gid = (b - NB_E) * 256 + tid;
        if (gid < TW * NN) {
            int t = gid / NN, n = gid - t * NN;
            const float4* xp = (const float4*)(x + ((size_t)t * NN + n) * 16);
            float4 a = xp[0], bb = xp[1], c = xp[2], d = xp[3];
            __align__(16) __half2 h[8];
            h[0] = __floats2half2_rn(a.x, a.y);  h[1] = __floats2half2_rn(a.z, a.w);
            h[2] = __floats2half2_rn(bb.x, bb.y); h[3] = __floats2half2_rn(bb.z, bb.w);
            h[4] = __floats2half2_rn(c.x, c.y);  h[5] = __floats2half2_rn(c.z, c.w);
            h[6] = __floats2half2_rn(d.x, d.y);  h[7] = __floats2half2_rn(d.z, d.w);
            const uint4* src = (const uint4*)h;
            uint4* dst = (uint4*)(g_xsh + (size_t)n * 192 + t * 16);
            dst[0] = src[0];
            dst[1] = src[1];
        }
    } else if (b < NB_E + NB_X + NB_F) {
        int f = (b - NB_E - NB_X) * 256 + tid;
        int co = f & 31, ci = (f >> 5) & 15, tk = f >> 9;
        int t = tk / 3, k = tk % 3;
        float acc = 0.f;
        #pragma unroll
        for (int cm = 0; cm < CMID; cm++)
            acc = fmaf(gw[(t * CI_N + ci) * CMID + cm], cw[(co * CMID + cm) * 3 + k], acc);
        g_M[((t * 3 + k) * CI_N + ci) * COUT + co] = acc;
    } else {
        int g = (b - NB_E - NB_X - NB_F) * 256 + tid;
        if (g < TW * COUT) {
            int co = g & 31, w = g >> 5;
            float acc = cb[co];
            #pragma unroll
            for (int k = 0; k < 3; k++) {
                int t = w + k - 1;
                if (t >= 0 && t < TW)
                    #pragma unroll
                    for (int cm = 0; cm < CMID; cm++)
                        acc = fmaf(gb[t * CMID + cm], cw[(co * CMID + cm) * 3 + k], acc);
            }
            g_B[w * COUT + co] = acc;
        }
    }
}

// ================= K2: single-pass exclusive scan (decoupled lookback) ================
__global__ __launch_bounds__(1024) void k_scan() {
    __shared__ int wsum[33];
    __shared__ int s_prefix;
    const int tid = threadIdx.x, lane = tid & 31, wid = tid >> 5, bid = blockIdx.x;
    const int i = bid * 1024 + tid;
    int v = (i < NN) ? g_cnt[i] : 0;
    int incl = v;
    #pragma unroll
    for (int d = 1; d < 32; d <<= 1) {
        int t = __shfl_up_sync(0xffffffffu, incl, d);
        if (lane >= d) incl += t;
    }
    if (lane == 31) wsum[wid] = incl;
    __syncthreads();
    if (wid == 0) {
        int x  = wsum[lane];
        int ix = x;
        #pragma unroll
        for (int d = 1; d < 32; d <<= 1) {
            int t = __shfl_up_sync(0xffffffffu, ix, d);
            if (lane >= d) ix += t;
        }
        wsum[lane] = ix - x;
        if (lane == 31) wsum[32] = ix;
    }
    __syncthreads();
    const int excl  = wsum[wid] + incl - v;
    const int total = wsum[32];

    if (tid == 0) {
        unsigned long long pk = ((unsigned long long)(bid == 0 ? 2u : 1u) << 32)
                              | (unsigned)total;
        atomicExch(&g_stat[bid], pk);
        if (bid == 0) s_prefix = 0;
    }
    if (bid != 0 && wid == 0) {
        volatile unsigned long long* vs = g_stat;
        int pred = bid - 1;
        int run = 0;
        for (;;) {
            int idx = pred - lane;
            unsigned long long st;
            if (idx >= 0) {
                do { st = vs[idx]; } while ((unsigned)(st >> 32) == 0u);
            } else {
                st = (2ull << 32);
            }
            unsigned flag = (unsigned)(st >> 32);
            int      val  = (int)(unsigned)st;
            unsigned mask = __ballot_sync(0xffffffffu, flag == 2u);
            if (mask) {
                int L = __ffs(mask) - 1;
                int contrib = (lane <= L) ? val : 0;
                #pragma unroll
                for (int d = 16; d >= 1; d >>= 1)
                    contrib += __shfl_xor_sync(0xffffffffu, contrib, d);
                run += contrib;
                break;
            } else {
                int contrib = val;
                #pragma unroll
                for (int d = 16; d >= 1; d >>= 1)
                    contrib += __shfl_xor_sync(0xffffffffu, contrib, d);
                run += contrib;
                pred -= 32;
            }
        }
        if (lane == 0) {
            s_prefix = run;
            atomicExch(&g_stat[bid], (2ull << 32) | (unsigned)(run + total));
        }
    }
    __syncthreads();
    const int pre = s_prefix;
    if (i < NN) {
        int o = excl + pre;
        g_off[i] = o;
        g_cur[i] = o;
    }
    if (bid == NSCAN - 1 && tid == 0) g_off[NN] = EE;
}

// ================= K3: scatter edges into dst-sorted CSR ==============================
__global__ void k_scatter(const int* __restrict__ A, const float* __restrict__ ew) {
    int e = blockIdx.x * blockDim.x + threadIdx.x;
    if (e < EE) {
        int r = A[e], c = A[EE + e];
        float dr = g_deg[r], dc = g_deg[c];
        float ir = dr > 0.f ? rsqrtf(dr) : 0.f;
        float ic = dc > 0.f ? rsqrtf(dc) : 0.f;
        int idx = atomicAdd(&g_cur[c], 1);
        g_edge[idx] = make_float2(__int_as_float(r), ir * ew[e] * ic);
    }
}

// ================= K4: aggregation (warp per dst, 4-edge unroll, 4 acc sets) ==========
__global__ void k_agg() {
    const int lane = threadIdx.x & 31, wid = threadIdx.x >> 5;
    const int dst = blockIdx.x * 8 + wid;              // 12500*8 == NN
    const int e0 = g_off[dst], e1 = g_off[dst + 1];
    float2 A0{0,0}, A1{0,0}, A2{0,0};
    float2 B0{0,0}, B1{0,0}, B2{0,0};
    float2 C0{0,0}, C1{0,0}, C2{0,0};
    float2 D0{0,0}, D1{0,0}, D2{0,0};
    const unsigned int* xb = (const unsigned int*)g_xsh;   // half2 units, 96/node
    int e = e0;
    for (; e + 3 < e1; e += 4) {
        float2 d0 = g_edge[e],     d1 = g_edge[e + 1];
        float2 d2 = g_edge[e + 2], d3 = g_edge[e + 3];
        const unsigned int* p0 = xb + (size_t)__float_as_int(d0.x) * 96 + lane;
        const unsigned int* p1 = xb + (size_t)__float_as_int(d1.x) * 96 + lane;
        const unsigned int* p2 = xb + (size_t)__float_as_int(d2.x) * 96 + lane;
        const unsigned int* p3 = xb + (size_t)__float_as_int(d3.x) * 96 + lane;
        unsigned int u00 = p0[0], u01 = p0[32], u02 = p0[64];
        unsigned int u10 = p1[0], u11 = p1[32], u12 = p1[64];
        unsigned int u20 = p2[0], u21 = p2[32], u22 = p2[64];
        unsigned int u30 = p3[0], u31 = p3[32], u32_ = p3[64];
        float2 v;
        v = __half22float2(*(const __half2*)&u00);
        A0.x = fmaf(d0.y, v.x, A0.x); A0.y = fmaf(d0.y, v.y, A0.y);
        v = __half22float2(*(const __half2*)&u01);
        A1.x = fmaf(d0.y, v.x, A1.x); A1.y = fmaf(d0.y, v.y, A1.y);
        v = __half22float2(*(const __half2*)&u02);
        A2.x = fmaf(d0.y, v.x, A2.x); A2.y = fmaf(d0.y, v.y, A2.y);
        v = __half22float2(*(const __half2*)&u10);
        B0.x = fmaf(d1.y, v.x, B0.x); B0.y = fmaf(d1.y, v.y, B0.y);
        v = __half22float2(*(const __half2*)&u11);
        B1.x = fmaf(d1.y, v.x, B1.x); B1.y = fmaf(d1.y, v.y, B1.y);
        v = __half22float2(*(const __half2*)&u12);
        B2.x = fmaf(d1.y, v.x, B2.x); B2.y = fmaf(d1.y, v.y, B2.y);
        v = __half22float2(*(const __half2*)&u20);
        C0.x = fmaf(d2.y, v.x, C0.x); C0.y = fmaf(d2.y, v.y, C0.y);
        v = __half22float2(*(const __half2*)&u21);
        C1.x = fmaf(d2.y, v.x, C1.x); C1.y = fmaf(d2.y, v.y, C1.y);
        v = __half22float2(*(const __half2*)&u22);
        C2.x = fmaf(d2.y, v.x, C2.x); C2.y = fmaf(d2.y, v.y, C2.y);
        v = __half22float2(*(const __half2*)&u30);
        D0.x = fmaf(d3.y, v.x, D0.x); D0.y = fmaf(d3.y, v.y, D0.y);
        v = __half22float2(*(const __half2*)&u31);
        D1.x = fmaf(d3.y, v.x, D1.x); D1.y = fmaf(d3.y, v.y, D1.y);
        v = __half22float2(*(const __half2*)&u32_);
        D2.x = fmaf(d3.y, v.x, D2.x); D2.y = fmaf(d3.y, v.y, D2.y);
    }
    for (; e < e1; e++) {
        float2 ed = g_edge[e];
        const unsigned int* p = xb + (size_t)__float_as_int(ed.x) * 96 + lane;
        unsigned int u0 = p[0], u1 = p[32], u2 = p[64];
        float2 v;
        v = __half22float2(*(const __half2*)&u0);
        A0.x = fmaf(ed.y, v.x, A0.x); A0.y = fmaf(ed.y, v.y, A0.y);
        v = __half22float2(*(const __half2*)&u1);
        A1.x = fmaf(ed.y, v.x, A1.x); A1.y = fmaf(ed.y, v.y, A1.y);
        v = __half22float2(*(const __half2*)&u2);
        A2.x = fmaf(ed.y, v.x, A2.x); A2.y = fmaf(ed.y, v.y, A2.y);
    }
    A0.x += B0.x + C0.x + D0.x;  A0.y += B0.y + C0.y + D0.y;
    A1.x += B1.x + C1.x + D1.x;  A1.y += B1.y + C1.y + D1.y;
    A2.x += B2.x + C2.x + D2.x;  A2.y += B2.y + C2.y + D2.y;
    float2* q = (float2*)(g_ax + (size_t)dst * 192) + lane;
    q[0] = A0; q[32] = A1; q[64] = A2;
}

// ================= K5: output GEMM per w; duplicated f32x2 weights in smem ============
// block: 256 threads, 256 nodes (128 pairs), one w. Thread: pair p = tid>>1,
// co half h = tid&1 (16 co). Inner loop: LDS.64 xv + LDS.128 Gd + FFMA2 only.
#define ONPB 256
#define OPAIRS 128
#define OSM2 ((48 * 32 * 2 + 48 * OPAIRS * 2 + 32) * 4)   // 61.6 KB
__global__ __launch_bounds__(256, 3)
void k_out(float* __restrict__ out) {
    extern __shared__ __align__(16) float sm[];
    unsigned long long* Gd = (unsigned long long*)sm;            // [48*32] dup pairs
    unsigned long long* Xp = Gd + 48 * 32;                       // [48*OPAIRS] node pairs
    float* Bs = (float*)(Xp + 48 * OPAIRS);                      // [32]
    const int w   = blockIdx.y;
    const int n0  = blockIdx.x * ONPB;
    const int tid = threadIdx.x;

    // weights, duplicated into f32x2 pairs (kills per-FMA packing movs)
    for (int u = tid; u < 48 * 32; u += 256) {
        int r = u >> 5, co = u & 31;
        int k = r >> 4, ci = r & 15;
        int t = w - 1 + k;
        float v = (t >= 0 && t < TW) ? g_M[((t * 3 + k) * CI_N + ci) * COUT + co] : 0.f;
        ((float2*)Gd)[u] = make_float2(v, v);
    }
    if (tid < 32) Bs[tid] = g_B[w * COUT + tid];

    // node pairs: Xp[r*OPAIRS + p] = (ax[2p][r], ax[2p+1][r]) within the w-window
    for (int u = tid; u < OPAIRS * 12; u += 256) {
        int p = u / 12, j = u - p * 12;
        int fo = (w - 1) * 16 + 4 * j;
        int na = n0 + 2 * p, nb = na + 1;
        float4 a = make_float4(0.f, 0.f, 0.f, 0.f), b = a;
        if (fo >= 0 && fo < 192) {
            if (na < NN) a = *(const float4*)(g_ax + (size_t)na * 192 + fo);
            if (nb < NN) b = *(const float4*)(g_ax + (size_t)nb * 192 + fo);
        }
        ((float2*)Xp)[(4 * j + 0) * OPAIRS + p] = make_float2(a.x, b.x);
        ((float2*)Xp)[(4 * j + 1) * OPAIRS + p] = make_float2(a.y, b.y);
        ((float2*)Xp)[(4 * j + 2) * OPAIRS + p] = make_float2(a.z, b.z);
        ((float2*)Xp)[(4 * j + 3) * OPAIRS + p] = make_float2(a.w, b.w);
    }
    __syncthreads();

    const int p = tid >> 1;
    const int h = tid & 1;
    unsigned long long acc[16];
    #pragma unroll
    for (int j = 0; j < 16; j++) acc[j] = 0ull;

    const unsigned long long* gbase = Gd + h * 16;
    #pragma unroll 6
    for (int r = 0; r < 48; r++) {
        unsigned long long xv = Xp[r * OPAIRS + p];
        const unsigned long long* g = gbase + r * 32;
        #pragma unroll
        for (int j = 0; j < 16; j++)
            acc[j] = fma2(xv, g[j], acc[j]);
    }

    const int na = n0 + 2 * p, nb = na + 1;
    float o0[16], o1[16];
    #pragma unroll
    for (int j = 0; j < 16; j++) {
        float lo, hi;
        upk2(lo, hi, acc[j]);
        float bv = Bs[h * 16 + j];
        lo += bv; hi += bv;
        o0[j] = lo >= 0.f ? lo : 0.01f * lo;
        o1[j] = hi >= 0.f ? hi : 0.01f * hi;
    }
    if (na < NN) {
        float* dst = out + (size_t)na * (TW * COUT) + w * COUT + h * 16;
        *(float4*)(dst + 0)  = make_float4(o0[0],  o0[1],  o0[2],  o0[3]);
        *(float4*)(dst + 4)  = make_float4(o0[4],  o0[5],  o0[6],  o0[7]);
        *(float4*)(dst + 8)  = make_float4(o0[8],  o0[9],  o0[10], o0[11]);
        *(float4*)(dst + 12) = make_float4(o0[12], o0[13], o0[14], o0[15]);
    }
    if (nb < NN) {
        float* dst = out + (size_t)nb * (TW * COUT) + w * COUT + h * 16;
        *(float4*)(dst + 0)  = make_float4(o1[0],  o1[1],  o1[2],  o1[3]);
        *(float4*)(dst + 4)  = make_float4(o1[4],  o1[5],  o1[6],  o1[7]);
        *(float4*)(dst + 8)  = make_float4(o1[8],  o1[9],  o1[10], o1[11]);
        *(float4*)(dst + 12) = make_float4(o1[12], o1[13], o1[14], o1[15]);
    }
}

extern "C" void kernel_launch(void* const* d_in, const int* in_sizes, int n_in,
                              void* d_out, int out_size) {
    const float* x  = (const float*)d_in[0];   // [W,N,16]
    const int*   A  = (const int*)  d_in[1];   // [2,E]
    const float* ew = (const float*)d_in[2];   // [E]
    const float* gw = (const float*)d_in[3];   // [W,16,32]
    const float* gb = (const float*)d_in[4];   // [W,32]
    const float* cw = (const float*)d_in[5];   // [32,32,3]
    const float* cb = (const float*)d_in[6];   // [32]
    float* out = (float*)d_out;                // [N,W,32]

    cudaFuncSetAttribute(k_out, cudaFuncAttributeMaxDynamicSharedMemorySize, OSM2);

    void *p_deg, *p_cnt, *p_stat;
    cudaGetSymbolAddress(&p_deg,  g_deg);
    cudaGetSymbolAddress(&p_cnt,  g_cnt);
    cudaGetSymbolAddress(&p_stat, g_stat);
    cudaMemsetAsync(p_deg,  0, NN * sizeof(float));
    cudaMemsetAsync(p_cnt,  0, NN * sizeof(int));
    cudaMemsetAsync(p_stat, 0, NSCAN * sizeof(unsigned long long));

    k_mega   <<<NB_E + NB_X + NB_F + NB_B, 256>>>(x, A, ew, gw, cw, gb, cb);
    k_scan   <<<NSCAN, 1024>>>();
    k_scatter<<<(EE + 255) / 256, 256>>>(A, ew);
    k_agg    <<<NN / 8, 256>>>();
    k_out    <<<dim3((NN + ONPB - 1) / ONPB, TW), 256, OSM2>>>(out);
}

// round 9
// speedup vs baseline: 1.1610x; 1.1610x over previous
#include <cuda_runtime.h>
#include <cuda_fp16.h>

#define NN   100000
#define EE   1600000
#define TW   12
#define CI_N 16
#define CMID 32
#define COUT 32

#define NSCAN 98                      // ceil(NN/1024)

// ---- scratch (allocation-free rule: __device__ globals) ----
__device__ float  g_deg[NN];
__device__ int    g_cnt[NN];
__device__ int    g_off[NN + 1];
__device__ int    g_cur[NN];
__device__ unsigned long long g_stat[NSCAN];         // decoupled-lookback state
__device__ float2 g_edge[EE];                        // (src as int bits, norm)
__device__ __half g_xsh[(size_t)NN * TW * CI_N];     // x node-major fp16
__device__ float  g_ax [(size_t)NN * TW * CI_N];     // aggregated x fp32
__device__ float  g_M  [TW * 3 * CI_N * COUT];       // fused gcn_w @ conv_w
__device__ float  g_B  [TW * COUT];                  // fused bias

// ---- packed f32x2 helpers (Blackwell FFMA2) ----
__device__ __forceinline__ void upk2(float& lo, float& hi, unsigned long long v) {
    asm("mov.b64 {%0, %1}, %2;" : "=f"(lo), "=f"(hi) : "l"(v));
}
__device__ __forceinline__ unsigned long long fma2(unsigned long long a,
                                                   unsigned long long b,
                                                   unsigned long long c) {
    unsigned long long d;
    asm("fma.rn.f32x2 %0, %1, %2, %3;" : "=l"(d) : "l"(a), "l"(b), "l"(c));
    return d;
}

// ================= K1: mega (deg histogram | x transpose | weight fuse | bias) ========
#define NB_E 6250                      // 6250*256 == EE
#define NB_X 4688                      // covers TW*NN = 1.2M
#define NB_F 72
#define NB_B 2
__global__ void k_mega(const float* __restrict__ x, const int* __restrict__ A,
                       const float* __restrict__ ew, const float* __restrict__ gw,
                       const float* __restrict__ cw, const float* __restrict__ gb,
                       const float* __restrict__ cb) {
    const int b = blockIdx.x, tid = threadIdx.x;
    if (b < NB_E) {
        int e = b * 256 + tid;
        int c = A[EE + e];
        atomicAdd(&g_deg[c], ew[e]);
        atomicAdd(&g_cnt[c], 1);
    } else if (b < NB_E + NB_X) {
        int gid = (b - NB_E) * 256 + tid;
        if (gid < TW * NN) {
            int t = gid / NN, n = gid - t * NN;
            const float4* xp = (const float4*)(x + ((size_t)t * NN + n) * 16);
            float4 a = xp[0], bb = xp[1], c = xp[2], d = xp[3];
            __align__(16) __half2 h[8];
            h[0] = __floats2half2_rn(a.x, a.y);  h[1] = __floats2half2_rn(a.z, a.w);
            h[2] = __floats2half2_rn(bb.x, bb.y); h[3] = __floats2half2_rn(bb.z, bb.w);
            h[4] = __floats2half2_rn(c.x, c.y);  h[5] = __floats2half2_rn(c.z, c.w);
            h[6] = __floats2half2_rn(d.x, d.y);  h[7] = __floats2half2_rn(d.z, d.w);
            const uint4* src = (const uint4*)h;
            uint4* dst = (uint4*)(g_xsh + (size_t)n * 192 + t * 16);
            dst[0] = src[0];
            dst[1] = src[1];
        }
    } else if (b < NB_E + NB_X + NB_F) {
        int f = (b - NB_E - NB_X) * 256 + tid;
        int co = f & 31, ci = (f >> 5) & 15, tk = f >> 9;
        int t = tk / 3, k = tk % 3;
        float acc = 0.f;
        #pragma unroll
        for (int cm = 0; cm < CMID; cm++)
            acc = fmaf(gw[(t * CI_N + ci) * CMID + cm], cw[(co * CMID + cm) * 3 + k], acc);
        g_M[((t * 3 + k) * CI_N + ci) * COUT + co] = acc;
    } else {
        int g = (b - NB_E - NB_X - NB_F) * 256 + tid;
        if (g < TW * COUT) {
            int co = g & 31, w = g >> 5;
            float acc = cb[co];
            #pragma unroll
            for (int k = 0; k < 3; k++) {
                int t = w + k - 1;
                if (t >= 0 && t < TW)
                    #pragma unroll
                    for (int cm = 0; cm < CMID; cm++)
                        acc = fmaf(gb[t * CMID + cm], cw[(co * CMID + cm) * 3 + k], acc);
            }
            g_B[w * COUT + co] = acc;
        }
    }
}

// ================= K2: single-pass exclusive scan (decoupled lookback) ================
__global__ __launch_bounds__(1024) void k_scan() {
    __shared__ int wsum[33];
    __shared__ int s_prefix;
    const int tid = threadIdx.x, lane = tid & 31, wid = tid >> 5, bid = blockIdx.x;
    const int i = bid * 1024 + tid;
    int v = (i < NN) ? g_cnt[i] : 0;
    int incl = v;
    #pragma unroll
    for (int d = 1; d < 32; d <<= 1) {
        int t = __shfl_up_sync(0xffffffffu, incl, d);
        if (lane >= d) incl += t;
    }
    if (lane == 31) wsum[wid] = incl;
    __syncthreads();
    if (wid == 0) {
        int x  = wsum[lane];
        int ix = x;
        #pragma unroll
        for (int d = 1; d < 32; d <<= 1) {
            int t = __shfl_up_sync(0xffffffffu, ix, d);
            if (lane >= d) ix += t;
        }
        wsum[lane] = ix - x;
        if (lane == 31) wsum[32] = ix;
    }
    __syncthreads();
    const int excl  = wsum[wid] + incl - v;
    const int total = wsum[32];

    if (tid == 0) {
        unsigned long long pk = ((unsigned long long)(bid == 0 ? 2u : 1u) << 32)
                              | (unsigned)total;
        atomicExch(&g_stat[bid], pk);
        if (bid == 0) s_prefix = 0;
    }
    if (bid != 0 && wid == 0) {
        volatile unsigned long long* vs = g_stat;
        int pred = bid - 1;
        int run = 0;
        for (;;) {
            int idx = pred - lane;
            unsigned long long st;
            if (idx >= 0) {
                do { st = vs[idx]; } while ((unsigned)(st >> 32) == 0u);
            } else {
                st = (2ull << 32);
            }
            unsigned flag = (unsigned)(st >> 32);
            int      val  = (int)(unsigned)st;
            unsigned mask = __ballot_sync(0xffffffffu, flag == 2u);
            if (mask) {
                int L = __ffs(mask) - 1;
                int contrib = (lane <= L) ? val : 0;
                #pragma unroll
                for (int d = 16; d >= 1; d >>= 1)
                    contrib += __shfl_xor_sync(0xffffffffu, contrib, d);
                run += contrib;
                break;
            } else {
                int contrib = val;
                #pragma unroll
                for (int d = 16; d >= 1; d >>= 1)
                    contrib += __shfl_xor_sync(0xffffffffu, contrib, d);
                run += contrib;
                pred -= 32;
            }
        }
        if (lane == 0) {
            s_prefix = run;
            atomicExch(&g_stat[bid], (2ull << 32) | (unsigned)(run + total));
        }
    }
    __syncthreads();
    const int pre = s_prefix;
    if (i < NN) {
        int o = excl + pre;
        g_off[i] = o;
        g_cur[i] = o;
    }
    if (bid == NSCAN - 1 && tid == 0) g_off[NN] = EE;
}

// ================= K3: scatter edges into dst-sorted CSR ==============================
__global__ void k_scatter(const int* __restrict__ A, const float* __restrict__ ew) {
    int e = blockIdx.x * blockDim.x + threadIdx.x;
    if (e < EE) {
        int r = A[e], c = A[EE + e];
        float dr = g_deg[r], dc = g_deg[c];
        float ir = dr > 0.f ? rsqrtf(dr) : 0.f;
        float ic = dc > 0.f ? rsqrtf(dc) : 0.f;
        int idx = atomicAdd(&g_cur[c], 1);
        g_edge[idx] = make_float2(__int_as_float(r), ir * ew[e] * ic);
    }
}

// ================= K4: aggregation (warp per dst, 2-edge unroll, dual acc) ============
// (exact revert to the 68.9us round-7-measured version)
__global__ void k_agg() {
    const int lane = threadIdx.x & 31, wid = threadIdx.x >> 5;
    const int dst = blockIdx.x * 8 + wid;              // 12500*8 == NN
    const int e0 = g_off[dst], e1 = g_off[dst + 1];
    float2 a0 = {0.f, 0.f}, a1 = {0.f, 0.f}, a2 = {0.f, 0.f};
    float2 b0 = {0.f, 0.f}, b1 = {0.f, 0.f}, b2 = {0.f, 0.f};
    const unsigned int* xb = (const unsigned int*)g_xsh;   // half2 units, 96/node
    int e = e0;
    for (; e + 1 < e1; e += 2) {
        float2 ed0 = g_edge[e];
        float2 ed1 = g_edge[e + 1];
        int   s0 = __float_as_int(ed0.x), s1 = __float_as_int(ed1.x);
        float w0 = ed0.y,                 w1 = ed1.y;
        const unsigned int* p0 = xb + (size_t)s0 * 96 + lane;
        const unsigned int* p1 = xb + (size_t)s1 * 96 + lane;
        unsigned int u00 = p0[0], u01 = p0[32], u02 = p0[64];
        unsigned int u10 = p1[0], u11 = p1[32], u12 = p1[64];
        float2 v;
        v = __half22float2(*(const __half2*)&u00);
        a0.x = fmaf(w0, v.x, a0.x); a0.y = fmaf(w0, v.y, a0.y);
        v = __half22float2(*(const __half2*)&u01);
        a1.x = fmaf(w0, v.x, a1.x); a1.y = fmaf(w0, v.y, a1.y);
        v = __half22float2(*(const __half2*)&u02);
        a2.x = fmaf(w0, v.x, a2.x); a2.y = fmaf(w0, v.y, a2.y);
        v = __half22float2(*(const __half2*)&u10);
        b0.x = fmaf(w1, v.x, b0.x); b0.y = fmaf(w1, v.y, b0.y);
        v = __half22float2(*(const __half2*)&u11);
        b1.x = fmaf(w1, v.x, b1.x); b1.y = fmaf(w1, v.y, b1.y);
        v = __half22float2(*(const __half2*)&u12);
        b2.x = fmaf(w1, v.x, b2.x); b2.y = fmaf(w1, v.y, b2.y);
    }
    if (e < e1) {
        float2 ed = g_edge[e];
        int   s = __float_as_int(ed.x);
        float w = ed.y;
        const unsigned int* p = xb + (size_t)s * 96 + lane;
        unsigned int u0 = p[0], u1 = p[32], u2 = p[64];
        float2 v;
        v = __half22float2(*(const __half2*)&u0);
        a0.x = fmaf(w, v.x, a0.x); a0.y = fmaf(w, v.y, a0.y);
        v = __half22float2(*(const __half2*)&u1);
        a1.x = fmaf(w, v.x, a1.x); a1.y = fmaf(w, v.y, a1.y);
        v = __half22float2(*(const __half2*)&u2);
        a2.x = fmaf(w, v.x, a2.x); a2.y = fmaf(w, v.y, a2.y);
    }
    a0.x += b0.x; a0.y += b0.y;
    a1.x += b1.x; a1.y += b1.y;
    a2.x += b2.x; a2.y += b2.y;
    float2* q = (float2*)(g_ax + (size_t)dst * 192) + lane;
    q[0] = a0; q[32] = a1; q[64] = a2;
}

// ================= K5: output GEMM per w; dup f32x2 weights, no spills ================
// 256 threads, 256 nodes (128 pairs), one w per block.
// Thread: pair p = tid&127, co-half h = tid>>7 (16 co). Warp = 32 consecutive pairs,
// same h -> weight LDS are pure broadcasts; inner loop = LDS + FFMA2 only.
#define OPAIRS 128
#define ONPB   256
#define OSM3   (48 * 32 * 8 + 48 * OPAIRS * 8 + 32 * 4)     // 61568 B
__global__ __launch_bounds__(256, 2)
void k_out(float* __restrict__ out) {
    extern __shared__ __align__(16) float sm[];
    unsigned long long* Gd = (unsigned long long*)sm;        // [48][32] dup pairs
    unsigned long long* Xp = Gd + 48 * 32;                   // [48][128] node pairs
    float* Bs = (float*)(Xp + 48 * OPAIRS);                  // [32]
    const int w   = blockIdx.y;
    const int n0  = blockIdx.x * ONPB;
    const int tid = threadIdx.x;

    // weights duplicated into f32x2 pairs (no per-FMA packing movs)
    for (int u = tid; u < 48 * 32; u += 256) {
        int r = u >> 5, co = u & 31;
        int k = r >> 4, ci = r & 15;
        int t = w - 1 + k;
        float v = (t >= 0 && t < TW) ? g_M[((t * 3 + k) * CI_N + ci) * COUT + co] : 0.f;
        ((float2*)Gd)[u] = make_float2(v, v);
    }
    if (tid < 32) Bs[tid] = g_B[w * COUT + tid];

    // node pairs: Xp[r*OPAIRS + p] = (ax[2p][row], ax[2p+1][row]) within w-window
    for (int u = tid; u < OPAIRS * 12; u += 256) {
        int p = u / 12, j = u - p * 12;
        int fo = (w - 1) * 16 + 4 * j;
        int na = n0 + 2 * p, nb = na + 1;
        float4 a = make_float4(0.f, 0.f, 0.f, 0.f), b = a;
        if (fo >= 0 && fo < 192) {
            if (na < NN) a = *(const float4*)(g_ax + (size_t)na * 192 + fo);
            if (nb < NN) b = *(const float4*)(g_ax + (size_t)nb * 192 + fo);
        }
        ((float2*)Xp)[(4 * j + 0) * OPAIRS + p] = make_float2(a.x, b.x);
        ((float2*)Xp)[(4 * j + 1) * OPAIRS + p] = make_float2(a.y, b.y);
        ((float2*)Xp)[(4 * j + 2) * OPAIRS + p] = make_float2(a.z, b.z);
        ((float2*)Xp)[(4 * j + 3) * OPAIRS + p] = make_float2(a.w, b.w);
    }
    __syncthreads();

    const int p = tid & 127;
    const int h = tid >> 7;
    unsigned long long acc[16];
    #pragma unroll
    for (int j = 0; j < 16; j++) acc[j] = 0ull;

    const unsigned long long* gbase = Gd + h * 16;
    #pragma unroll 4
    for (int r = 0; r < 48; r++) {
        unsigned long long xv = Xp[r * OPAIRS + p];
        const unsigned long long* g = gbase + r * 32;
        #pragma unroll
        for (int j = 0; j < 16; j++)
            acc[j] = fma2(xv, g[j], acc[j]);
    }

    // streaming epilogue: 4 co at a time, no big live arrays
    const int na = n0 + 2 * p, nb = na + 1;
    float* dsta = out + (size_t)na * (TW * COUT) + w * COUT + h * 16;
    float* dstb = out + (size_t)nb * (TW * COUT) + w * COUT + h * 16;
    #pragma unroll
    for (int jg = 0; jg < 4; jg++) {
        float l0, h0, l1, h1, l2, h2, l3, h3;
        upk2(l0, h0, acc[4 * jg + 0]);
        upk2(l1, h1, acc[4 * jg + 1]);
        upk2(l2, h2, acc[4 * jg + 2]);
        upk2(l3, h3, acc[4 * jg + 3]);
        float b0 = Bs[h * 16 + 4 * jg + 0], b1 = Bs[h * 16 + 4 * jg + 1];
        float b2 = Bs[h * 16 + 4 * jg + 2], b3 = Bs[h * 16 + 4 * jg + 3];
        l0 += b0; l1 += b1; l2 += b2; l3 += b3;
        h0 += b0; h1 += b1; h2 += b2; h3 += b3;
        l0 = l0 >= 0.f ? l0 : 0.01f * l0;  l1 = l1 >= 0.f ? l1 : 0.01f * l1;
        l2 = l2 >= 0.f ? l2 : 0.01f * l2;  l3 = l3 >= 0.f ? l3 : 0.01f * l3;
        h0 = h0 >= 0.f ? h0 : 0.01f * h0;  h1 = h1 >= 0.f ? h1 : 0.01f * h1;
        h2 = h2 >= 0.f ? h2 : 0.01f * h2;  h3 = h3 >= 0.f ? h3 : 0.01f * h3;
        if (na < NN) *(float4*)(dsta + 4 * jg) = make_float4(l0, l1, l2, l3);
        if (nb < NN) *(float4*)(dstb + 4 * jg) = make_float4(h0, h1, h2, h3);
    }
}

extern "C" void kernel_launch(void* const* d_in, const int* in_sizes, int n_in,
                              void* d_out, int out_size) {
    const float* x  = (const float*)d_in[0];   // [W,N,16]
    const int*   A  = (const int*)  d_in[1];   // [2,E]
    const float* ew = (const float*)d_in[2];   // [E]
    const float* gw = (const float*)d_in[3];   // [W,16,32]
    const float* gb = (const float*)d_in[4];   // [W,32]
    const float* cw = (const float*)d_in[5];   // [32,32,3]
    const float* cb = (const float*)d_in[6];   // [32]
    float* out = (float*)d_out;                // [N,W,32]

    cudaFuncSetAttribute(k_out, cudaFuncAttributeMaxDynamicSharedMemorySize, OSM3);

    void *p_deg, *p_cnt, *p_stat;
    cudaGetSymbolAddress(&p_deg,  g_deg);
    cudaGetSymbolAddress(&p_cnt,  g_cnt);
    cudaGetSymbolAddress(&p_stat, g_stat);
    cudaMemsetAsync(p_deg,  0, NN * sizeof(float));
    cudaMemsetAsync(p_cnt,  0, NN * sizeof(int));
    cudaMemsetAsync(p_stat, 0, NSCAN * sizeof(unsigned long long));

    k_mega   <<<NB_E + NB_X + NB_F + NB_B, 256>>>(x, A, ew, gw, cw, gb, cb);
    k_scan   <<<NSCAN, 1024>>>();
    k_scatter<<<(EE + 255) / 256, 256>>>(A, ew);
    k_agg    <<<NN / 8, 256>>>();
    k_out    <<<dim3((NN + ONPB - 1) / ONPB, TW), 256, OSM3>>>(out);
}